// round 1
// baseline (speedup 1.0000x reference)
#include <cuda_runtime.h>
#include <math_constants.h>

#define B    32
#define NN   2000
#define TD   384     // 24*16
#define E    64
#define TT   24
#define DD   16

#define BR   32      // query rows per CTA
#define BC   32      // kv rows per tile
#define KSTRIDE 68   // k_s row stride (floats), conflict-friendly, float4-aligned
#define SSTRIDE 33
#define PSTRIDE 36

// ---- scratch (no allocations allowed; __device__ globals are the sanctioned path)
__device__ float g_q1[B * NN * E];   // 16 MB
__device__ float g_k1[B * NN * E];   // 16 MB

// ============================================================
// Kernel 1: q1 = LN(xf@Wq + bq), k1 = LN(xf@Wk + bk)
// 8 rows per CTA, 128 threads: t<64 -> q col t, t>=64 -> k col t-64
// ============================================================
__global__ __launch_bounds__(128) void qk_ln_kernel(
    const float* __restrict__ x,
    const float* __restrict__ Wq, const float* __restrict__ bq,
    const float* __restrict__ Wk, const float* __restrict__ bk,
    const float* __restrict__ g0, const float* __restrict__ beta0,
    const float* __restrict__ g1, const float* __restrict__ beta1)
{
    __shared__ float xs[8 * TD];        // 12 KB
    __shared__ float qk[8 * 128];       // 4 KB
    __shared__ float mu_s[16], rs_s[16];

    const int tid = threadIdx.x;
    const long base = (long)blockIdx.x * 8;   // 64000 rows / 8 = 8000 CTAs exact

    const float* xp = x + base * TD;
    for (int idx = tid; idx < 8 * TD; idx += 128) xs[idx] = xp[idx];
    __syncthreads();

    const int col = tid & 63;
    const int isK = tid >> 6;
    const float* __restrict__ W = isK ? Wk : Wq;
    const float bias = isK ? bk[col] : bq[col];

    float acc[8];
#pragma unroll
    for (int r = 0; r < 8; r++) acc[r] = bias;

    const float4* xs4 = (const float4*)xs;
    for (int i4 = 0; i4 < TD / 4; i4++) {
        float4 w4;
        w4.x = W[(i4 * 4 + 0) * E + col];
        w4.y = W[(i4 * 4 + 1) * E + col];
        w4.z = W[(i4 * 4 + 2) * E + col];
        w4.w = W[(i4 * 4 + 3) * E + col];
#pragma unroll
        for (int r = 0; r < 8; r++) {
            float4 xv = xs4[r * (TD / 4) + i4];
            acc[r] += xv.x * w4.x + xv.y * w4.y + xv.z * w4.z + xv.w * w4.w;
        }
    }
#pragma unroll
    for (int r = 0; r < 8; r++) qk[r * 128 + isK * 64 + col] = acc[r];
    __syncthreads();

    if (tid < 16) {
        int r = tid & 7, k = tid >> 3;
        const float* v = &qk[r * 128 + k * 64];
        float s = 0.f, s2 = 0.f;
        for (int j = 0; j < 64; j++) { float t = v[j]; s += t; s2 += t * t; }
        float mu = s * (1.0f / 64.0f);
        float var = s2 * (1.0f / 64.0f) - mu * mu;
        mu_s[tid] = mu;
        rs_s[tid] = rsqrtf(var + 1e-5f);
    }
    __syncthreads();

    const float gg  = isK ? g1[col] : g0[col];
    const float bb  = isK ? beta1[col] : beta0[col];
    float* __restrict__ outp = isK ? g_k1 : g_q1;
#pragma unroll
    for (int r = 0; r < 8; r++) {
        float mu = mu_s[isK * 8 + r], rs = rs_s[isK * 8 + r];
        outp[(base + r) * E + col] = (qk[r * 128 + isK * 64 + col] - mu) * rs * gg + bb;
    }
}

// ============================================================
// Kernel 2: flash attention over nodes + fused RPPsAtt epilogue
// CTA: (row-tile of 32, batch). 256 threads: rg = tid>>5 (4 rows each),
// cgi = tid&31 (12 output cols each). acc = 4 rows x 12 cols per thread.
// ============================================================

// smem float offsets
#define OFF_Q   0                          // 32*64   = 2048
#define OFF_K   2048                       // 32*68   = 2176
#define OFF_NS  (OFF_K + BC * KSTRIDE)     // 4224, 32*384 = 12288
#define OFF_S   (OFF_NS + BC * TD)         // 16512, 32*33 = 1056
#define OFF_P   (OFF_S + BR * SSTRIDE)     // 17568, 32*36 = 1152
#define OFF_M   (OFF_P + BC * PSTRIDE)     // 18720
#define OFF_L   (OFF_M + BR)               // 18752
#define OFF_A   (OFF_L + BR)               // 18784
#define OFF_W   (OFF_A + BR)               // 18816, 32*24 = 768
#define SMEM_FLOATS (OFF_W + BR * TT)      // 19584
#define SMEM_BYTES  (SMEM_FLOATS * 4)      // 78336

static __device__ __forceinline__ void fma12(float4& a0, float4& a1, float4& a2,
                                             float p, float4 b0, float4 b1, float4 b2) {
    a0.x += p * b0.x; a0.y += p * b0.y; a0.z += p * b0.z; a0.w += p * b0.w;
    a1.x += p * b1.x; a1.y += p * b1.y; a1.z += p * b1.z; a1.w += p * b1.w;
    a2.x += p * b2.x; a2.y += p * b2.y; a2.z += p * b2.z; a2.w += p * b2.w;
}
static __device__ __forceinline__ void scl12(float4& a0, float4& a1, float4& a2, float s) {
    a0.x *= s; a0.y *= s; a0.z *= s; a0.w *= s;
    a1.x *= s; a1.y *= s; a1.z *= s; a1.w *= s;
    a2.x *= s; a2.y *= s; a2.z *= s; a2.w *= s;
}

__global__ __launch_bounds__(256) void attn_kernel(
    const float* __restrict__ x,
    const float* __restrict__ normal,
    const float* __restrict__ Win,
    float* __restrict__ out)
{
    extern __shared__ float sm[];
    float* q_s = sm + OFF_Q;
    float* k_s = sm + OFF_K;
    float* ns  = sm + OFF_NS;
    float* S_s = sm + OFF_S;
    float* p_s = sm + OFF_P;
    float* m_s = sm + OFF_M;
    float* l_s = sm + OFF_L;
    float* a_s = sm + OFF_A;
    float* w_s = sm + OFF_W;

    const int tid = threadIdx.x;
    const int b   = blockIdx.y;
    const int n0  = blockIdx.x * BR;
    int nrows = NN - n0; if (nrows > BR) nrows = BR;
    const int rg  = tid >> 5;
    const int cgi = tid & 31;
    const int rb  = rg * 4;

    // init q tile / stats / p buffer
    const float* q1p = g_q1 + ((long)b * NN + n0) * E;
    for (int idx = tid; idx < BR * E; idx += 256) {
        int r = idx >> 6;
        q_s[idx] = (r < nrows) ? q1p[idx] : 0.f;
    }
    if (tid < BR) { m_s[tid] = -CUDART_INF_F; l_s[tid] = 0.f; a_s[tid] = 1.f; }
    for (int idx = tid; idx < BC * PSTRIDE; idx += 256) p_s[idx] = 0.f;

    float4 acc[4][3];
#pragma unroll
    for (int i = 0; i < 4; i++)
#pragma unroll
        for (int j = 0; j < 3; j++) acc[i][j] = make_float4(0.f, 0.f, 0.f, 0.f);

    const float inv_sqrt_n = rsqrtf((float)NN);
    const float4* k1p4 = (const float4*)(g_k1 + (long)b * NN * E);
    const float4* nrm4 = (const float4*)normal;

    const int ntiles = (NN + BC - 1) / BC;
    for (int mt = 0; mt < ntiles; mt++) {
        const int m0 = mt * BC;
        int mrows = NN - m0; if (mrows > BC) mrows = BC;
        __syncthreads();   // previous readers done before overwrite

        // K tile: 32 rows x 64 floats = 512 float4
        for (int idx = tid; idx < BC * 16; idx += 256) {
            int mm = idx >> 4, j4 = idx & 15;
            float4 v = (mm < mrows) ? k1p4[(m0 + mm) * 16 + j4] : make_float4(0, 0, 0, 0);
            ((float4*)&k_s[mm * KSTRIDE])[j4] = v;
        }
        // V tile (normal): 32 rows x 384 floats = 3072 float4
        for (int idx = tid; idx < BC * 96; idx += 256) {
            int mm = idx / 96, c4 = idx % 96;
            float4 v = (mm < mrows) ? nrm4[(m0 + mm) * 96 + c4] : make_float4(0, 0, 0, 0);
            ((float4*)ns)[mm * 96 + c4] = v;
        }
        __syncthreads();

        // ---- S = q . k  (each thread: 4 rows x its m'=cgi)
        {
            float d0 = 0.f, d1 = 0.f, d2 = 0.f, d3 = 0.f;
            const float4* kq  = (const float4*)&k_s[cgi * KSTRIDE];
            const float4* q0p = (const float4*)&q_s[(rb + 0) * E];
            const float4* q1r = (const float4*)&q_s[(rb + 1) * E];
            const float4* q2p = (const float4*)&q_s[(rb + 2) * E];
            const float4* q3p = (const float4*)&q_s[(rb + 3) * E];
#pragma unroll
            for (int j4 = 0; j4 < 16; j4++) {
                float4 kv = kq[j4];
                float4 a0 = q0p[j4], a1 = q1r[j4], a2 = q2p[j4], a3 = q3p[j4];
                d0 += a0.x * kv.x + a0.y * kv.y + a0.z * kv.z + a0.w * kv.w;
                d1 += a1.x * kv.x + a1.y * kv.y + a1.z * kv.z + a1.w * kv.w;
                d2 += a2.x * kv.x + a2.y * kv.y + a2.z * kv.z + a2.w * kv.w;
                d3 += a3.x * kv.x + a3.y * kv.y + a3.z * kv.z + a3.w * kv.w;
            }
            if (cgi < mrows) {
                S_s[(rb + 0) * SSTRIDE + cgi] = d0 * inv_sqrt_n;
                S_s[(rb + 1) * SSTRIDE + cgi] = d1 * inv_sqrt_n;
                S_s[(rb + 2) * SSTRIDE + cgi] = d2 * inv_sqrt_n;
                S_s[(rb + 3) * SSTRIDE + cgi] = d3 * inv_sqrt_n;
            } else {
                S_s[(rb + 0) * SSTRIDE + cgi] = -1e30f;
                S_s[(rb + 1) * SSTRIDE + cgi] = -1e30f;
                S_s[(rb + 2) * SSTRIDE + cgi] = -1e30f;
                S_s[(rb + 3) * SSTRIDE + cgi] = -1e30f;
            }
        }
        __syncthreads();

        // ---- per-row online-softmax stats (exp computed once)
        if (tid < BR && tid < nrows) {
            const int r = tid;
            float mold = m_s[r];
            float tm = mold;
#pragma unroll
            for (int m = 0; m < BC; m++) tm = fmaxf(tm, S_s[r * SSTRIDE + m]);
            float alpha = __expf(mold - tm);   // first tile: exp(-inf)=0
            float lsum = 0.f;
#pragma unroll
            for (int m = 0; m < BC; m++) {
                float p = __expf(S_s[r * SSTRIDE + m] - tm);
                p_s[m * PSTRIDE + r] = p;
                lsum += p;
            }
            l_s[r] = l_s[r] * alpha + lsum;
            m_s[r] = tm;
            a_s[r] = alpha;
        }
        __syncthreads();

        // ---- rescale + P@V microkernel (4 rows x 12 cols per thread)
        {
            const float al0 = a_s[rb + 0], al1 = a_s[rb + 1];
            const float al2 = a_s[rb + 2], al3 = a_s[rb + 3];
            scl12(acc[0][0], acc[0][1], acc[0][2], al0);
            scl12(acc[1][0], acc[1][1], acc[1][2], al1);
            scl12(acc[2][0], acc[2][1], acc[2][2], al2);
            scl12(acc[3][0], acc[3][1], acc[3][2], al3);

            const float4* nsp = (const float4*)ns;
#pragma unroll 4
            for (int m = 0; m < BC; m++) {
                float4 pv = *((const float4*)&p_s[m * PSTRIDE + rb]);
                float4 b0 = nsp[m * 96 + cgi * 3 + 0];
                float4 b1 = nsp[m * 96 + cgi * 3 + 1];
                float4 b2 = nsp[m * 96 + cgi * 3 + 2];
                fma12(acc[0][0], acc[0][1], acc[0][2], pv.x, b0, b1, b2);
                fma12(acc[1][0], acc[1][1], acc[1][2], pv.y, b0, b1, b2);
                fma12(acc[2][0], acc[2][1], acc[2][2], pv.z, b0, b1, b2);
                fma12(acc[3][0], acc[3][1], acc[3][2], pv.w, b0, b1, b2);
            }
        }
    }
    __syncthreads();

    // ---- finalize: data = acc / l, stash rows into ns buffer (reuse V smem)
#pragma unroll
    for (int i = 0; i < 4; i++) {
        float l = l_s[rb + i];
        float li = 1.f / l;                 // invalid rows: NaN, never read
        float4 v0 = acc[i][0], v1 = acc[i][1], v2 = acc[i][2];
        scl12(v0, v1, v2, li);
        float4* dst = (float4*)&ns[(rb + i) * TD + cgi * 12];
        dst[0] = v0; dst[1] = v1; dst[2] = v2;
    }
    __syncthreads();

    // ---- RPPsAtt: query = x[:, :, -1, :] @ Win; softmax over t of query.data
    if (tid < nrows) {
        const int r = tid;
        const int n = n0 + r;
        const float* xl = x + (((long)b * NN + n) * TD) + (TT - 1) * DD;
        float q16[DD];
#pragma unroll
        for (int dp = 0; dp < DD; dp++) {
            float s = 0.f;
#pragma unroll
            for (int d = 0; d < DD; d++) s += xl[d] * Win[d * DD + dp];
            q16[dp] = s;
        }
        float att[TT]; float mx = -CUDART_INF_F;
#pragma unroll
        for (int t = 0; t < TT; t++) {
            float s = 0.f;
#pragma unroll
            for (int d = 0; d < DD; d++) s += q16[d] * ns[r * TD + t * DD + d];
            att[t] = s; mx = fmaxf(mx, s);
        }
        float se = 0.f;
#pragma unroll
        for (int t = 0; t < TT; t++) { float e = __expf(att[t] - mx); att[t] = e; se += e; }
        float si = 1.f / se;
#pragma unroll
        for (int t = 0; t < TT; t++) w_s[r * TT + t] = att[t] * si;
    }
    __syncthreads();

    // ---- out = data + weight[..., None]
    float* outp = out + ((long)b * NN + n0) * TD;
    for (int idx = tid; idx < nrows * TD; idx += 256) {
        int r = idx / TD;
        int c = idx - r * TD;
        outp[idx] = ns[idx] + w_s[r * TT + (c >> 4)];
    }
}

// ============================================================
extern "C" void kernel_launch(void* const* d_in, const int* in_sizes, int n_in,
                              void* d_out, int out_size)
{
    (void)in_sizes; (void)n_in; (void)out_size;
    const float* x     = (const float*)d_in[0];
    const float* Wq    = (const float*)d_in[1];
    const float* bq    = (const float*)d_in[2];
    const float* Wk    = (const float*)d_in[3];
    const float* bk    = (const float*)d_in[4];
    const float* g0    = (const float*)d_in[5];
    const float* beta0 = (const float*)d_in[6];
    const float* g1    = (const float*)d_in[7];
    const float* beta1 = (const float*)d_in[8];
    const float* nrm   = (const float*)d_in[9];
    const float* Win   = (const float*)d_in[10];
    float* out = (float*)d_out;

    cudaFuncSetAttribute(attn_kernel, cudaFuncAttributeMaxDynamicSharedMemorySize, SMEM_BYTES);

    qk_ln_kernel<<<(B * NN) / 8, 128>>>(x, Wq, bq, Wk, bk, g0, beta0, g1, beta1);

    dim3 grid((NN + BR - 1) / BR, B);
    attn_kernel<<<grid, 256, SMEM_BYTES>>>(x, nrm, Win, out);
}

// round 2
// speedup vs baseline: 1.1770x; 1.1770x over previous
#include <cuda_runtime.h>
#include <cstdint>

#define B    32
#define NN   2000
#define TD   384
#define E    64
#define TT   24
#define DD   16

#define BRR  64      // query rows per CTA
#define BCC  32      // kv rows per tile
#define NT   63      // ceil(NN/BCC)
#define KST  68      // k row stride (floats): stride%32==4 -> conflict-free LDS.128
#define VST  384     // v row stride (natural; lane word-stride 12 -> conflict-free)
#define PST  66      // p row stride in u64 (64 data + 2 pad)
#define OST  388     // stage row stride (floats)
#define OST4 97

// attn smem layout (floats)
#define O_Q  0                         // 64*64        = 4096
#define O_K  4096                      // 3 * 32*68    = 6528
#define O_V  10624                     // 3 * 32*384   = 36864
#define O_P  47488                     // 32*66 u64    = 4224 floats
#define SM_FLOATS 51712
#define SM_BYTES (SM_FLOATS*4)         // 206848 B

#define K1_ROWS 32
#define K1_SM_FLOATS (K1_ROWS*TD + K1_ROWS*128 + 128)
#define K1_SM_BYTES (K1_SM_FLOATS*4)   // 66560 B

typedef unsigned long long u64;

// scratch (device globals: the sanctioned no-alloc path)
__device__ float g_q1[B*NN*E];   // 16 MB
__device__ float g_k1[B*NN*E];   // 16 MB

// ---------- packed f32x2 helpers ----------
__device__ __forceinline__ u64 pack2(float a, float b){
    u64 r; asm("mov.b64 %0,{%1,%2};" : "=l"(r) : "f"(a), "f"(b)); return r;
}
__device__ __forceinline__ void ffma2(u64 &d, u64 a, u64 b){
    asm("fma.rn.f32x2 %0,%1,%2,%0;" : "+l"(d) : "l"(a), "l"(b));
}
__device__ __forceinline__ float2 unpack2(u64 v){
    float2 r; asm("mov.b64 {%0,%1},%2;" : "=f"(r.x), "=f"(r.y) : "l"(v)); return r;
}
__device__ __forceinline__ unsigned smaddr(const void* p){
    return (unsigned)__cvta_generic_to_shared(p);
}
__device__ __forceinline__ void cpa16(unsigned d, const void* s){
    asm volatile("cp.async.cg.shared.global [%0],[%1],16;" :: "r"(d), "l"(s));
}

// ============================================================
// Kernel 1: q1 = LN(xf@Wq + bq), k1 = LN(xf@Wk + bk)
// 32 rows/CTA, 128 threads: t<64 -> q col t, t>=64 -> k col t-64
// ============================================================
__global__ __launch_bounds__(128) void qk_ln_kernel(
    const float* __restrict__ x,
    const float* __restrict__ Wq, const float* __restrict__ bq,
    const float* __restrict__ Wk, const float* __restrict__ bk,
    const float* __restrict__ g0, const float* __restrict__ beta0,
    const float* __restrict__ g1, const float* __restrict__ beta1)
{
    extern __shared__ float sm1[];
    float* xs = sm1;                   // 32*384
    float* qk = sm1 + K1_ROWS*TD;      // 32*128
    float* st = qk + K1_ROWS*128;      // 128
    const int tid = threadIdx.x;
    const long base = (long)blockIdx.x * K1_ROWS;   // 2000 CTAs exact

    const float4* xp4 = (const float4*)(x + base*TD);
    for (int i = tid; i < K1_ROWS*96; i += 128) ((float4*)xs)[i] = xp4[i];
    __syncthreads();

    const int col = tid & 63;
    const int isK = tid >> 6;
    const float* __restrict__ W = isK ? Wk : Wq;

    u64 acc2[K1_ROWS];
#pragma unroll
    for (int r = 0; r < K1_ROWS; r++) acc2[r] = 0ull;

    for (int i4 = 0; i4 < 96; i4++) {
        float w0 = W[(4*i4+0)*E + col];
        float w1 = W[(4*i4+1)*E + col];
        float w2 = W[(4*i4+2)*E + col];
        float w3 = W[(4*i4+3)*E + col];
        u64 wa = pack2(w0, w1), wb = pack2(w2, w3);
#pragma unroll
        for (int r = 0; r < K1_ROWS; r++) {
            ulonglong2 xv = ((const ulonglong2*)(xs + r*TD))[i4];  // broadcast across CTA
            ffma2(acc2[r], xv.x, wa);
            ffma2(acc2[r], xv.y, wb);
        }
    }
    const float bias = isK ? bk[col] : bq[col];
#pragma unroll
    for (int r = 0; r < K1_ROWS; r++) {
        float2 f = unpack2(acc2[r]);
        qk[r*128 + isK*64 + col] = f.x + f.y + bias;
    }
    __syncthreads();

    if (tid < 64) {
        int r = tid & 31, h = tid >> 5;
        const float* v = qk + r*128 + h*64;
        float s = 0.f, s2 = 0.f;
#pragma unroll
        for (int j = 0; j < 64; j++) { float t = v[(j + r) & 63]; s += t; s2 += t*t; }
        float mu = s * (1.f/64.f);
        float var = s2 * (1.f/64.f) - mu*mu;
        st[h*32 + r] = mu;
        st[64 + h*32 + r] = rsqrtf(var + 1e-5f);
    }
    __syncthreads();

    const float gg = isK ? g1[col] : g0[col];
    const float bb = isK ? beta1[col] : beta0[col];
    float* __restrict__ outp = isK ? g_k1 : g_q1;
#pragma unroll 8
    for (int r = 0; r < K1_ROWS; r++) {
        float mu = st[isK*32 + r], rs = st[64 + isK*32 + r];
        outp[(base + r)*E + col] = (qk[r*128 + isK*64 + col] - mu) * rs * gg + bb;
    }
}

// ============================================================
// Kernel 2: flash attention (no max: |S|<=1.43 since q,k are LN'd)
// BR=64 rows/CTA, 256 threads, 1 CTA/SM.
// Thread (rg=tid>>5, cgi=tid&31): 8 rows (rg*8..+7), 12 out cols (cgi*12..).
// S-phase: thread computes 8 rows vs m=cgi, exp fused, p stored duplicated (f32x2).
// Triple-buffered cp.async prefetch of K/V tiles.
// ============================================================
__device__ __forceinline__ void prefetch_tile(float* sm, int tid, int t,
        const float4* k1p4, const float4* nrm4)
{
    if (t < NT) {
        int s = t - (t/3)*3;
        int m0 = t * BCC;
        float* kd = sm + O_K + s*(BCC*KST);
        float* vd = sm + O_V + s*(BCC*VST);
#pragma unroll
        for (int i = 0; i < 2; i++) {          // 512 float4 K
            int idx = tid + i*256;
            int mm = idx >> 4, j4 = idx & 15;
            int g = m0 + mm; if (g >= NN) g = NN - 1;
            cpa16(smaddr(kd + mm*KST + j4*4), k1p4 + (size_t)g*16 + j4);
        }
#pragma unroll
        for (int i = 0; i < 12; i++) {         // 3072 float4 V
            int idx = tid + i*256;
            int mm = idx / 96, c4 = idx - mm*96;
            int g = m0 + mm; if (g >= NN) g = NN - 1;
            cpa16(smaddr(vd + mm*VST + c4*4), nrm4 + (size_t)g*96 + c4);
        }
    }
    asm volatile("cp.async.commit_group;");
}

__global__ __launch_bounds__(256, 1) void attn_kernel(
    const float* __restrict__ x,
    const float* __restrict__ normal,
    const float* __restrict__ Win,
    float* __restrict__ out)
{
    extern __shared__ float sm[];
    const int tid = threadIdx.x;
    const int b   = blockIdx.y;
    const int n0  = blockIdx.x * BRR;
    const int rg  = tid >> 5, cgi = tid & 31, rb = rg*8;

    const float4* q1p4 = (const float4*)(g_q1 + (size_t)b*NN*E);
    const float4* k1p4 = (const float4*)(g_k1 + (size_t)b*NN*E);
    const float4* nrm4 = (const float4*)normal;

    // load q tile (clamped rows; padded rows harmless: p finite, stores guarded)
    for (int i = tid; i < BRR*16; i += 256) {
        int r = i >> 4, j4 = i & 15;
        int g = n0 + r; if (g >= NN) g = NN - 1;
        ((float4*)(sm + O_Q))[i] = q1p4[(size_t)g*16 + j4];
    }
    prefetch_tile(sm, tid, 0, k1p4, nrm4);
    prefetch_tile(sm, tid, 1, k1p4, nrm4);

    u64 acc[8][6];
#pragma unroll
    for (int r = 0; r < 8; r++)
#pragma unroll
        for (int c = 0; c < 6; c++) acc[r][c] = 0ull;
    float lacc[8];
#pragma unroll
    for (int r = 0; r < 8; r++) lacc[r] = 0.f;

    u64* p_u = (u64*)(sm + O_P);
    const float scale = 0.022360679774997897f;   // 1/sqrt(2000)

    for (int t = 0; t < NT; t++) {
        int s = t - (t/3)*3;
        asm volatile("cp.async.wait_group 1;");
        __syncthreads();

        // ---- S = q.k, exp, store p (duplicated pairs) ----
        {
            const ulonglong2* kk = (const ulonglong2*)(sm + O_K + s*(BCC*KST) + cgi*KST);
            u64 dacc[8];
#pragma unroll
            for (int r = 0; r < 8; r++) dacc[r] = 0ull;
#pragma unroll
            for (int j2 = 0; j2 < 16; j2++) {
                ulonglong2 kv = kk[j2];
#pragma unroll
                for (int r = 0; r < 8; r++) {
                    ulonglong2 qv = ((const ulonglong2*)(sm + O_Q + (rb + r)*E))[j2];
                    ffma2(dacc[r], qv.x, kv.x);
                    ffma2(dacc[r], qv.y, kv.y);
                }
            }
            const bool mval = (t*BCC + cgi) < NN;
            u64 pp[8];
#pragma unroll
            for (int r = 0; r < 8; r++) {
                float2 f = unpack2(dacc[r]);
                float p = mval ? __expf((f.x + f.y) * scale) : 0.f;
                lacc[r] += p;
                pp[r] = pack2(p, p);
            }
            ulonglong2* ps = (ulonglong2*)(p_u + cgi*PST + rb);
            ulonglong2 w0; w0.x = pp[0]; w0.y = pp[1]; ps[0] = w0;
            ulonglong2 w1; w1.x = pp[2]; w1.y = pp[3]; ps[1] = w1;
            ulonglong2 w2; w2.x = pp[4]; w2.y = pp[5]; ps[2] = w2;
            ulonglong2 w3; w3.x = pp[6]; w3.y = pp[7]; ps[3] = w3;
        }
        __syncthreads();
        prefetch_tile(sm, tid, t + 2, k1p4, nrm4);

        // ---- PV: acc[8 rows][12 cols] += p * v ----
        {
            const float* vb = sm + O_V + s*(BCC*VST) + cgi*12;
#pragma unroll 4
            for (int m = 0; m < BCC; m++) {
                const ulonglong2* vv = (const ulonglong2*)(vb + m*VST);
                ulonglong2 v0 = vv[0], v1 = vv[1], v2 = vv[2];
                const ulonglong2* pl = (const ulonglong2*)(p_u + m*PST + rb);  // broadcast
                ulonglong2 pA = pl[0], pB = pl[1], pC = pl[2], pD = pl[3];
                u64 pr[8] = {pA.x, pA.y, pB.x, pB.y, pC.x, pC.y, pD.x, pD.y};
#pragma unroll
                for (int r = 0; r < 8; r++) {
                    ffma2(acc[r][0], pr[r], v0.x);
                    ffma2(acc[r][1], pr[r], v0.y);
                    ffma2(acc[r][2], pr[r], v1.x);
                    ffma2(acc[r][3], pr[r], v1.y);
                    ffma2(acc[r][4], pr[r], v2.x);
                    ffma2(acc[r][5], pr[r], v2.y);
                }
            }
        }
    }

    // l: reduce across the 32 lanes (all lanes of a warp share the same rows)
#pragma unroll
    for (int r = 0; r < 8; r++) {
#pragma unroll
        for (int off = 16; off; off >>= 1)
            lacc[r] += __shfl_xor_sync(0xffffffffu, lacc[r], off);
    }
    __syncthreads();   // all warps done reading v buffers

    // stage data = acc / l  (reuse v area; stride 388 to soften epilogue conflicts)
    float* stage = sm + O_V;
#pragma unroll
    for (int r = 0; r < 8; r++) {
        float inv = 1.f / lacc[r];
        float4 o[3];
#pragma unroll
        for (int c = 0; c < 3; c++) {
            float2 a  = unpack2(acc[r][2*c]);
            float2 b2 = unpack2(acc[r][2*c + 1]);
            o[c] = make_float4(a.x*inv, a.y*inv, b2.x*inv, b2.y*inv);
        }
        float4* dst = (float4*)(stage + (rb + r)*OST + cgi*12);
        dst[0] = o[0]; dst[1] = o[1]; dst[2] = o[2];
    }
    __syncthreads();

    // RPPsAtt weights (per row)
    float* w_s = sm + O_P;   // reuse p area (needs 64*24 floats)
    if (tid < BRR) {
        int n = n0 + tid;
        if (n < NN) {
            const float* xl = x + ((size_t)b*NN + n)*TD + (TT - 1)*DD;
            float q16[DD];
#pragma unroll
            for (int dp = 0; dp < DD; dp++) {
                float sacc = 0.f;
#pragma unroll
                for (int d = 0; d < DD; d++) sacc += xl[d] * Win[d*DD + dp];
                q16[dp] = sacc;
            }
            const float* row = stage + tid*OST;
            float att[TT]; float mx = -1e30f;
#pragma unroll
            for (int tt2 = 0; tt2 < TT; tt2++) {
                float sacc = 0.f;
#pragma unroll
                for (int d = 0; d < DD; d++) sacc += q16[d] * row[tt2*DD + d];
                att[tt2] = sacc; mx = fmaxf(mx, sacc);
            }
            float se = 0.f;
#pragma unroll
            for (int tt2 = 0; tt2 < TT; tt2++) { float e = __expf(att[tt2] - mx); att[tt2] = e; se += e; }
            float si = 1.f / se;
#pragma unroll
            for (int tt2 = 0; tt2 < TT; tt2++) w_s[tid*TT + tt2] = att[tt2] * si;
        }
    }
    __syncthreads();

    // out = data + weight[..., None]
    int nrows = NN - n0; if (nrows > BRR) nrows = BRR;
    float4* outp = (float4*)(out + ((size_t)b*NN + n0)*TD);
    for (int i = tid; i < nrows*96; i += 256) {
        int r = i / 96, c4 = i - r*96;
        float4 v = ((const float4*)stage)[r*OST4 + c4];
        float w = w_s[r*TT + (c4 >> 2)];
        v.x += w; v.y += w; v.z += w; v.w += w;
        outp[i] = v;
    }
}

// ============================================================
extern "C" void kernel_launch(void* const* d_in, const int* in_sizes, int n_in,
                              void* d_out, int out_size)
{
    (void)in_sizes; (void)n_in; (void)out_size;
    const float* x     = (const float*)d_in[0];
    const float* Wq    = (const float*)d_in[1];
    const float* bq    = (const float*)d_in[2];
    const float* Wk    = (const float*)d_in[3];
    const float* bk    = (const float*)d_in[4];
    const float* g0    = (const float*)d_in[5];
    const float* beta0 = (const float*)d_in[6];
    const float* g1    = (const float*)d_in[7];
    const float* beta1 = (const float*)d_in[8];
    const float* nrm   = (const float*)d_in[9];
    const float* Win   = (const float*)d_in[10];
    float* out = (float*)d_out;

    cudaFuncSetAttribute(qk_ln_kernel, cudaFuncAttributeMaxDynamicSharedMemorySize, K1_SM_BYTES);
    cudaFuncSetAttribute(attn_kernel,  cudaFuncAttributeMaxDynamicSharedMemorySize, SM_BYTES);

    qk_ln_kernel<<<(B*NN)/K1_ROWS, 128, K1_SM_BYTES>>>(x, Wq, bq, Wk, bk, g0, beta0, g1, beta1);

    dim3 grid((NN + BRR - 1)/BRR, B);
    attn_kernel<<<grid, 256, SM_BYTES>>>(x, nrm, Win, out);
}